// round 9
// baseline (speedup 1.0000x reference)
#include <cuda_runtime.h>
#include <math.h>

// ---------------------------------------------------------------------------
// FourierDeformationPk: band-limited (|k|<=4) Fourier displacement synthesis
// + trilinear border-clamped grid sample.
//
// Key simplifications vs reference:
//  * irfftn of the sparse hermitian spectrum == sum of ~257 plane waves,
//    evaluated separably (kx -> ky -> kz stages) with precomputed twiddles.
//  * Hermitian symmetrization + rfft half-spectrum doubling == weight 2 on
//    every fed mode except DC (weight 1), taking Re() at the end.
//  * Coordinate normalization cancels: f{z,y,x} = clamp(idx - disp_c, 0, dim-1)
// ---------------------------------------------------------------------------

#define DD 32
#define HH 256
#define WW 256
#define NREAL (DD * HH * WW)          // 2097152
#define PLANE_HW (HH * WW)            // 65536
#define HALF_SPEC (32 * 256 * 129)    // 1056768
#define ROW_SPEC (256 * 129)          // 33024

// scratch (static device globals; no allocations)
__device__ float2 g_C[3 * 9 * 9 * 5];          // coefficient box
__device__ float2 g_T1[3 * 9 * 9 * 256];       // after kx contraction
__device__ float2 g_T2[3 * 9 * 256 * 256];     // after ky contraction (14.2 MB)
__device__ float2 g_tabX[5 * 256];
__device__ float2 g_tabY[9 * 256];
__device__ float2 g_tabZ[9 * 32];

// ---------------------------------------------------------------------------
// Kernel 1: zero coeff box, build twiddle tables, scatter fed coefficients.
// Single block.
// ---------------------------------------------------------------------------
__global__ void k_setup(const float* __restrict__ seeds,
                        const float* __restrict__ Pk,
                        const float* __restrict__ defscale,
                        const int* __restrict__ feed_idx,
                        int fdim) {
    int t = threadIdx.x;
    int nt = blockDim.x;

    for (int i = t; i < 3 * 9 * 9 * 5; i += nt) g_C[i] = make_float2(0.f, 0.f);

    // tabX[kx][x] = e^{2*pi*i*kx*x/256}
    for (int i = t; i < 5 * 256; i += nt) {
        int kx = i >> 8, x = i & 255;
        float s, c;
        sincospif((float)(kx * x) / 128.0f, &s, &c);
        g_tabX[i] = make_float2(c, s);
    }
    // tabY[iy][y] = e^{2*pi*i*(iy-4)*y/256}
    for (int i = t; i < 9 * 256; i += nt) {
        int iy = i >> 8, y = i & 255;
        float s, c;
        sincospif((float)((iy - 4) * y) / 128.0f, &s, &c);
        g_tabY[i] = make_float2(c, s);
    }
    // tabZ[iz][z] = e^{2*pi*i*(iz-4)*z/32}
    for (int i = t; i < 9 * 32; i += nt) {
        int iz = i >> 5, z = i & 31;
        float s, c;
        sincospif((float)((iz - 4) * z) / 16.0f, &s, &c);
        g_tabZ[i] = make_float2(c, s);
    }
    __syncthreads();

    const float invN = 1.0f / (float)NREAL;
    float ds0 = defscale[0], ds1 = defscale[1], ds2 = defscale[2];
    for (int j = t; j < fdim; j += nt) {
        int flat = feed_idx[j];
        int reim = flat / HALF_SPEC;
        int rest = flat - reim * HALF_SPEC;
        int z = rest / ROW_SPEC;
        int r2 = rest - z * ROW_SPEC;
        int y = r2 / 129;
        int x = r2 - y * 129;
        int kz = (z < 16) ? z : z - 32;
        int ky = (y < 128) ? y : y - 256;
        int iz = kz + 4, iy = ky + 4, ix = x;   // all in range by KCUT=4
        float w = (z == 0 && y == 0 && x == 0) ? 1.0f : 2.0f;
        float base = w * invN * Pk[j];
        float ds[3] = {ds0, ds1, ds2};
        #pragma unroll
        for (int c = 0; c < 3; c++) {
            float v = seeds[c * fdim + j] * ds[c] * base;
            float* slot = (float*)&g_C[((c * 9 + iz) * 9 + iy) * 5 + ix];
            slot[reim] = v;   // .x = real feed, .y = imag feed
        }
    }
}

// ---------------------------------------------------------------------------
// Kernel 2: contract over kx.  T1[m][x], m = (c*9+iz)*9+iy  (243 x 256)
// ---------------------------------------------------------------------------
__global__ void k_stageX() {
    int tid = blockIdx.x * blockDim.x + threadIdx.x;
    if (tid >= 3 * 9 * 9 * 256) return;
    int x = tid & 255;
    int m = tid >> 8;
    float2 acc = make_float2(0.f, 0.f);
    #pragma unroll
    for (int ix = 0; ix < 5; ix++) {
        float2 C = g_C[m * 5 + ix];
        float2 e = g_tabX[(ix << 8) + x];
        acc.x += C.x * e.x - C.y * e.y;
        acc.y += C.x * e.y + C.y * e.x;
    }
    g_T1[tid] = acc;
}

// ---------------------------------------------------------------------------
// Kernel 3: contract over ky.  T2[p][y][x], p = c*9+iz  (27 x 256 x 256)
// ---------------------------------------------------------------------------
__global__ void k_stageY() {
    int tid = blockIdx.x * blockDim.x + threadIdx.x;
    if (tid >= 27 * PLANE_HW) return;
    int x = tid & 255;
    int y = (tid >> 8) & 255;
    int p = tid >> 16;
    float2 acc = make_float2(0.f, 0.f);
    #pragma unroll
    for (int iy = 0; iy < 9; iy++) {
        float2 T = g_T1[(p * 9 + iy) * 256 + x];
        float2 e = g_tabY[(iy << 8) + y];
        acc.x += T.x * e.x - T.y * e.y;
        acc.y += T.x * e.y + T.y * e.x;
    }
    g_T2[tid] = acc;
}

// ---------------------------------------------------------------------------
// Kernel 4: fused kz contraction + trilinear border grid-sample.
// One thread per (y,x) per z-chunk of 8.  27 T2 complex values register-cached.
// ---------------------------------------------------------------------------
#define ZCHUNK 8
#define NZC (DD / ZCHUNK)   // 4

__global__ void __launch_bounds__(256) k_final(const float* __restrict__ fr,
                                               float* __restrict__ out) {
    int g = blockIdx.x * blockDim.x + threadIdx.x;
    int pix = g & (PLANE_HW - 1);
    int zc = g >> 16;
    int x = pix & 255;
    int y = pix >> 8;

    float2 t2[27];
    #pragma unroll
    for (int p = 0; p < 27; p++) t2[p] = g_T2[(p << 16) + pix];

    #pragma unroll
    for (int zz = 0; zz < ZCHUNK; zz++) {
        int z = (zc << 3) + zz;
        float d0 = 0.f, d1 = 0.f, d2 = 0.f;
        #pragma unroll
        for (int iz = 0; iz < 9; iz++) {
            float2 e = g_tabZ[(iz << 5) + z];      // uniform within warp
            d0 += t2[iz].x      * e.x - t2[iz].y      * e.y;
            d1 += t2[9 + iz].x  * e.x - t2[9 + iz].y  * e.y;
            d2 += t2[18 + iz].x * e.x - t2[18 + iz].y * e.y;
        }
        // grid_sample coords collapse to clamp(index - disp)
        float fz = fminf(fmaxf((float)z - d0, 0.f), 31.f);
        float fy = fminf(fmaxf((float)y - d1, 0.f), 255.f);
        float fx = fminf(fmaxf((float)x - d2, 0.f), 255.f);
        float z0f = floorf(fz), y0f = floorf(fy), x0f = floorf(fx);
        float wz = fz - z0f, wy = fy - y0f, wx = fx - x0f;
        int z0 = (int)z0f, y0 = (int)y0f, x0 = (int)x0f;
        int z1 = min(z0 + 1, 31), y1 = min(y0 + 1, 255), x1 = min(x0 + 1, 255);

        int b00 = (z0 << 16) + (y0 << 8);
        int b01 = (z0 << 16) + (y1 << 8);
        int b10 = (z1 << 16) + (y0 << 8);
        int b11 = (z1 << 16) + (y1 << 8);
        int o000 = b00 + x0, o001 = b00 + x1;
        int o010 = b01 + x0, o011 = b01 + x1;
        int o100 = b10 + x0, o101 = b10 + x1;
        int o110 = b11 + x0, o111 = b11 + x1;

        float uz = 1.f - wz, uy = 1.f - wy, ux = 1.f - wx;
        float w000 = uz * uy * ux, w001 = uz * uy * wx;
        float w010 = uz * wy * ux, w011 = uz * wy * wx;
        float w100 = wz * uy * ux, w101 = wz * uy * wx;
        float w110 = wz * wy * ux, w111 = wz * wy * wx;

        int outbase = (z << 16) + pix;
        #pragma unroll
        for (int bc = 0; bc < 12; bc++) {
            const float* p = fr + bc * NREAL;
            float v = p[o000] * w000 + p[o001] * w001
                    + p[o010] * w010 + p[o011] * w011
                    + p[o100] * w100 + p[o101] * w101
                    + p[o110] * w110 + p[o111] * w111;
            out[bc * NREAL + outbase] = v;
        }
    }
}

// ---------------------------------------------------------------------------
extern "C" void kernel_launch(void* const* d_in, const int* in_sizes, int n_in,
                              void* d_out, int out_size) {
    const float* fr       = (const float*)d_in[0];
    const float* seeds    = (const float*)d_in[1];
    const float* Pk       = (const float*)d_in[2];
    const float* defscale = (const float*)d_in[3];
    // d_in[4] = grid (unused: coordinate normalization cancels analytically)
    const int*   feed_idx = (const int*)d_in[5];
    int fdim = in_sizes[5];

    float* out = (float*)d_out;

    k_setup<<<1, 512>>>(seeds, Pk, defscale, feed_idx, fdim);
    k_stageX<<<(3 * 9 * 9 * 256 + 255) / 256, 256>>>();
    k_stageY<<<(27 * PLANE_HW) / 256, 256>>>();
    k_final<<<(NZC * PLANE_HW) / 256, 256>>>(fr, out);
}